// round 9
// baseline (speedup 1.0000x reference)
#include <cuda_runtime.h>
#include <cuda_bf16.h>

// SmallVDSR: 20-layer 3x3 conv stack on [8,1,512,512] fp32.
//   conv1: 1->8 + relu
//   conv2..19: 18x (8->8 + relu)   [hot kernel]
//   conv20: 8->1, no relu
//
// R8: constant-bank weights (R7) + RY=8 (weight reuse x8) to take the
// constant-port (LDC rt=8) off the critical path. Mid kernel: 32x32 tile,
// block (32,4) = 128 threads, 8 rows x 8 oc = 64 accumulators per thread.

#define H 512
#define W 512
#define NB 8
#define PLANE (H * W)

__device__ float g_bufA[NB * 8 * PLANE];
__device__ float g_bufB[NB * 8 * PLANE];

// Mid-layer weights, repacked [l][ic][tap][oc] (oc contiguous): 18*8*9*8 floats.
__constant__ float c_w[18 * 8 * 9 * 8];
__device__   float g_wpack[18 * 8 * 9 * 8];

__global__ void repack_weights_kernel(const float* __restrict__ wmid)
{
    int idx = blockIdx.x * blockDim.x + threadIdx.x;   // [l][ic][t][oc]
    if (idx >= 18 * 8 * 9 * 8) return;
    int oc = idx & 7;
    int t  = (idx >> 3) % 9;
    int ic = ((idx >> 3) / 9) & 7;
    int l  = idx / 576;
    // source layout: [l][oc][ic][ky][kx]
    g_wpack[idx] = wmid[l * 576 + (oc * 8 + ic) * 9 + t];
}

// ---------------------------------------------------------------------------
// Mid layers: 8 -> 8, relu. Constant-bank weights, RY=8.
// ---------------------------------------------------------------------------
__global__ void __launch_bounds__(128, 4)
conv3x3_88_kernel(const float* __restrict__ in,
                  float* __restrict__ out,
                  int lbase)                 // = layer * 576
{
    constexpr int TX = 32, TY = 32, RY = 8;
    constexpr int SW = TX + 2;            // 34
    constexpr int STILE = SW * (TY + 2);  // 1156

    __shared__ float s_in[8 * STILE];

    const int tx  = threadIdx.x;          // 0..31
    const int ty  = threadIdx.y;          // 0..3
    const int n   = blockIdx.z;
    const int gx0 = blockIdx.x * TX;
    const int gy0 = blockIdx.y * TY;

    const float* inb = in + (size_t)n * 8 * PLANE;

    // ---- stage input tile, division-free (34x34 with zero halo) ----
    {
        const int gxA = gx0 + tx - 1;
        const bool xokA = (gxA >= 0) && (gxA < W);
        const int gxB = gx0 + 32 + tx - 1;
        const bool xokB = (tx < 2) && (gxB < W);

        #pragma unroll 1
        for (int ic = 0; ic < 8; ++ic) {
            const float* src = inb + ic * PLANE;
            float* dstS = &s_in[ic * STILE];
            #pragma unroll
            for (int j = 0; j < 9; ++j) {        // rows ty + 4j, guard < 34
                int sy = ty + j * 4;
                if (sy >= 34) continue;
                int gy = gy0 + sy - 1;
                bool yok = (gy >= 0) && (gy < H);
                int rb = (gy << 9);
                dstS[sy * SW + tx] = (yok && xokA) ? src[rb + gxA] : 0.0f;
                if (tx < 2)
                    dstS[sy * SW + 32 + tx] = (yok && xokB) ? src[rb + gxB] : 0.0f;
            }
        }
    }

    __syncthreads();

    float acc[RY][8];
    #pragma unroll
    for (int ry = 0; ry < RY; ++ry)
        #pragma unroll
        for (int oc = 0; oc < 8; ++oc)
            acc[ry][oc] = 0.0f;

    const int y0 = ty * RY;
    const float* si0 = &s_in[y0 * SW + tx];

    #pragma unroll 1
    for (int ic = 0; ic < 8; ++ic) {
        const float* si = si0 + ic * STILE;
        const int wbase = lbase + ic * 72;    // uniform across block

        #pragma unroll
        for (int ky = 0; ky < 3; ++ky) {
            #pragma unroll
            for (int kx = 0; kx < 3; ++kx) {
                const int tb = wbase + (ky * 3 + kx) * 8;
                // uniform const-bank loads; each reused by 8 rows
                float w0 = c_w[tb + 0];
                float w1 = c_w[tb + 1];
                float w2 = c_w[tb + 2];
                float w3 = c_w[tb + 3];
                float w4 = c_w[tb + 4];
                float w5 = c_w[tb + 5];
                float w6 = c_w[tb + 6];
                float w7 = c_w[tb + 7];
                #pragma unroll
                for (int ry = 0; ry < RY; ++ry) {
                    float v = si[(ry + ky) * SW + kx];
                    acc[ry][0] = fmaf(v, w0, acc[ry][0]);
                    acc[ry][1] = fmaf(v, w1, acc[ry][1]);
                    acc[ry][2] = fmaf(v, w2, acc[ry][2]);
                    acc[ry][3] = fmaf(v, w3, acc[ry][3]);
                    acc[ry][4] = fmaf(v, w4, acc[ry][4]);
                    acc[ry][5] = fmaf(v, w5, acc[ry][5]);
                    acc[ry][6] = fmaf(v, w6, acc[ry][6]);
                    acc[ry][7] = fmaf(v, w7, acc[ry][7]);
                }
            }
        }
    }

    // ---- write out (relu) ----
    float* outb = out + (size_t)n * 8 * PLANE;
    #pragma unroll
    for (int ry = 0; ry < RY; ++ry) {
        int off = ((gy0 + y0 + ry) << 9) + gx0 + tx;
        #pragma unroll
        for (int oc = 0; oc < 8; ++oc)
            outb[oc * PLANE + off] = fmaxf(acc[ry][oc], 0.0f);
    }
}

// ---------------------------------------------------------------------------
// Generic scalar kernel (conv1: 1->8 relu, conv20: 8->1 no relu)
// ---------------------------------------------------------------------------
template <int IC, int OC, bool RELU>
__global__ void __launch_bounds__(256, 4)
conv3x3_kernel(const float* __restrict__ in,
               const float* __restrict__ wg,
               float* __restrict__ out)
{
    constexpr int TX = 32, TY = 32, RY = 4;
    constexpr int SW = TX + 2;
    constexpr int STILE = SW * (TY + 2);

    __shared__ float s_in[IC * STILE];
    __shared__ float s_w[IC * 9 * OC];

    const int tx  = threadIdx.x;
    const int ty  = threadIdx.y;
    const int tid = ty * 32 + tx;
    const int n   = blockIdx.z;
    const int gx0 = blockIdx.x * TX;
    const int gy0 = blockIdx.y * TY;

    const float* inb = in + (size_t)n * IC * PLANE;

    {
        const int gxA = gx0 + tx - 1;
        const bool xokA = (gxA >= 0) && (gxA < W);
        const int gxB = gx0 + 32 + tx - 1;
        const bool xokB = (tx < 2) && (gxB < W);

        #pragma unroll 1
        for (int ic = 0; ic < IC; ++ic) {
            const float* src = inb + ic * PLANE;
            float* dstS = &s_in[ic * STILE];
            #pragma unroll
            for (int j = 0; j < 5; ++j) {
                int sy = ty + j * 8;
                if (j == 4 && ty >= 2) continue;
                int gy = gy0 + sy - 1;
                bool yok = (gy >= 0) && (gy < H);
                int rb = (gy << 9);
                dstS[sy * SW + tx] = (yok && xokA) ? src[rb + gxA] : 0.0f;
                if (tx < 2)
                    dstS[sy * SW + 32 + tx] = (yok && xokB) ? src[rb + gxB] : 0.0f;
            }
        }
    }

    #pragma unroll 1
    for (int idx = tid; idx < IC * 9 * OC; idx += 256) {
        int oc = idx % OC;
        int t  = idx / OC;
        int ic = t / 9;
        int k  = t - ic * 9;
        s_w[idx] = wg[(oc * IC + ic) * 9 + k];
    }

    __syncthreads();

    float acc[RY][OC];
    #pragma unroll
    for (int ry = 0; ry < RY; ++ry)
        #pragma unroll
        for (int oc = 0; oc < OC; ++oc)
            acc[ry][oc] = 0.0f;

    const int y0 = ty * RY;
    const float* si0 = &s_in[y0 * SW + tx];

    #pragma unroll 1
    for (int ic = 0; ic < IC; ++ic) {
        const float* si = si0 + ic * STILE;
        const float* sw = &s_w[ic * 9 * OC];
        #pragma unroll
        for (int ky = 0; ky < 3; ++ky) {
            #pragma unroll
            for (int kx = 0; kx < 3; ++kx) {
                float wv[OC];
                #pragma unroll
                for (int oc = 0; oc < OC; ++oc)
                    wv[oc] = sw[(ky * 3 + kx) * OC + oc];
                #pragma unroll
                for (int ry = 0; ry < RY; ++ry) {
                    float v = si[(ry + ky) * SW + kx];
                    #pragma unroll
                    for (int oc = 0; oc < OC; ++oc)
                        acc[ry][oc] = fmaf(v, wv[oc], acc[ry][oc]);
                }
            }
        }
    }

    float* outb = out + (size_t)n * OC * PLANE;
    #pragma unroll
    for (int ry = 0; ry < RY; ++ry) {
        int off = ((gy0 + y0 + ry) << 9) + gx0 + tx;
        #pragma unroll
        for (int oc = 0; oc < OC; ++oc) {
            float v = acc[ry][oc];
            if (RELU) v = fmaxf(v, 0.0f);
            outb[oc * PLANE + off] = v;
        }
    }
}

extern "C" void kernel_launch(void* const* d_in, const int* in_sizes, int n_in,
                              void* d_out, int out_size)
{
    const float* x    = (const float*)d_in[0];  // [8,1,512,512]
    const float* w1   = (const float*)d_in[1];  // [8,1,3,3]
    const float* wmid = (const float*)d_in[2];  // [18,8,8,3,3]
    const float* w20  = (const float*)d_in[3];  // [1,8,3,3]
    float* out = (float*)d_out;                 // [8,1,512,512]

    float* bufA = nullptr;
    float* bufB = nullptr;
    float* wpack = nullptr;
    cudaGetSymbolAddress((void**)&bufA, g_bufA);
    cudaGetSymbolAddress((void**)&bufB, g_bufB);
    cudaGetSymbolAddress((void**)&wpack, g_wpack);

    // repack mid weights and stage them into the constant bank (capturable)
    repack_weights_kernel<<<(18 * 8 * 9 * 8 + 255) / 256, 256>>>(wmid);
    cudaMemcpyToSymbolAsync(c_w, wpack, 18 * 8 * 9 * 8 * sizeof(float), 0,
                            cudaMemcpyDeviceToDevice, 0);

    dim3 blockMid(32, 4);
    dim3 blockStd(32, 8);
    dim3 grid(W / 32, H / 32, NB);

    // conv1: 1 -> 8, relu
    conv3x3_kernel<1, 8, true><<<grid, blockStd>>>(x, w1, bufA);

    // conv2..19: 18x 8 -> 8, relu (constant-bank weights, RY=8)
    float* src = bufA;
    float* dst = bufB;
    for (int l = 0; l < 18; ++l) {
        conv3x3_88_kernel<<<grid, blockMid>>>(src, dst, l * 576);
        float* t = src; src = dst; dst = t;
    }

    // conv20: 8 -> 1, no relu
    conv3x3_kernel<8, 1, false><<<grid, blockStd>>>(src, w20, out);
}

// round 10
// speedup vs baseline: 2.0287x; 2.0287x over previous
#include <cuda_runtime.h>
#include <cuda_bf16.h>

// SmallVDSR: 20-layer 3x3 conv stack on [8,1,512,512] fp32.
//   conv1: 1->8 + relu
//   conv2..19: 18x (8->8 + relu)   [hot kernel]
//   conv20: 8->1, no relu
//
// R9 hot kernel: pixel-vectorized direct conv.
//   Block 256 = (32,8). Tile 128x8 outputs. Each thread: 4 consecutive px
//   (x) x 1 row x 8 oc = 32 accumulators. Inputs per ic arrive as
//   3 x (LDS.128 + LDS.64) = 6 wide loads covering 18 values feeding 288
//   FMAs. Weights from __constant__ bank as float4 (R7). Row pitch 132 for
//   16B alignment. Outputs as STG.128.

#define H 512
#define W 512
#define NB 8
#define PLANE (H * W)

__device__ float g_bufA[NB * 8 * PLANE];
__device__ float g_bufB[NB * 8 * PLANE];

// Mid-layer weights, repacked [l][ic][tap][oc] (oc contiguous): 18*8*9*8 floats.
__constant__ float c_w[18 * 8 * 9 * 8];
__device__   float g_wpack[18 * 8 * 9 * 8];

__global__ void repack_weights_kernel(const float* __restrict__ wmid)
{
    int idx = blockIdx.x * blockDim.x + threadIdx.x;   // [l][ic][t][oc]
    if (idx >= 18 * 8 * 9 * 8) return;
    int oc = idx & 7;
    int t  = (idx >> 3) % 9;
    int ic = ((idx >> 3) / 9) & 7;
    int l  = idx / 576;
    // source layout: [l][oc][ic][ky][kx]
    g_wpack[idx] = wmid[l * 576 + (oc * 8 + ic) * 9 + t];
}

// ---------------------------------------------------------------------------
// Mid layers: 8 -> 8, relu. Pixel-vectorized, constant-bank weights.
// ---------------------------------------------------------------------------
__global__ void __launch_bounds__(256, 4)
conv3x3_88_kernel(const float* __restrict__ in,
                  float* __restrict__ out,
                  int lbase)                 // = layer * 576
{
    constexpr int TW = 128;               // tile width (outputs)
    constexpr int TH = 8;                 // tile height (outputs)
    constexpr int PITCH = 132;            // halo row pitch (130 used, 16B-aligned)
    constexpr int STILE = PITCH * (TH + 2);   // 1320 floats per ic

    __shared__ __align__(16) float s_in[8 * STILE];

    const int tid  = threadIdx.x;
    const int tx   = tid & 31;            // 0..31 -> cols 4tx..4tx+3
    const int ty   = tid >> 5;            // 0..7  -> output row
    const int n    = blockIdx.z;
    const int gx0  = blockIdx.x * TW;
    const int gy0  = blockIdx.y * TH;

    const float* inb = in + (size_t)n * 8 * PLANE;

    // ---- stage input tile 130x10 per ic (zero halo), warp-per-row ----
    {
        const int wid  = tid >> 5;
        const int lane = tid & 31;
        #pragma unroll 1
        for (int ic = 0; ic < 8; ++ic) {
            const float* src = inb + ic * PLANE;
            float* dst = &s_in[ic * STILE];
            #pragma unroll
            for (int rr0 = 0; rr0 < 2; ++rr0) {
                int rr = wid + rr0 * 8;
                if (rr0 == 1 && wid >= 2) continue;    // rows 8,9 by warps 0,1
                int gy = gy0 + rr - 1;
                bool yok = (gy >= 0) && (gy < H);
                int rb = gy << 9;
                #pragma unroll
                for (int cc = 0; cc < 5; ++cc) {
                    int c = lane + cc * 32;
                    if (cc == 4 && lane >= 2) break;   // cols 0..129
                    int gx = gx0 + c - 1;
                    bool ok = yok && (gx >= 0) && (gx < W);
                    dst[rr * PITCH + c] = ok ? src[rb + gx] : 0.0f;
                }
            }
        }
    }

    __syncthreads();

    float acc[8][4];   // [oc][px]
    #pragma unroll
    for (int oc = 0; oc < 8; ++oc)
        #pragma unroll
        for (int j = 0; j < 4; ++j)
            acc[oc][j] = 0.0f;

    // thread's input window base: halo rows ty..ty+2, halo cols 4tx..4tx+5
    const float* si0 = &s_in[ty * PITCH + 4 * tx];

    #pragma unroll 1
    for (int ic = 0; ic < 8; ++ic) {
        const float* si = si0 + ic * STILE;
        const int wb_ic = lbase + ic * 72;

        #pragma unroll
        for (int r = 0; r < 3; ++r) {                  // input row = ky
            float4 v03 = *(const float4*)(si + r * PITCH);
            float2 v45 = *(const float2*)(si + r * PITCH + 4);
            float v0 = v03.x, v1 = v03.y, v2 = v03.z, v3 = v03.w;
            float v4 = v45.x, v5 = v45.y;

            #pragma unroll
            for (int kx = 0; kx < 3; ++kx) {
                const int tb = wb_ic + (r * 3 + kx) * 8;
                float4 wa = *(const float4*)&c_w[tb];       // oc 0..3
                float4 wc = *(const float4*)&c_w[tb + 4];   // oc 4..7

                // px j uses v[j + kx]
                float u0 = (kx == 0) ? v0 : ((kx == 1) ? v1 : v2);
                float u1 = (kx == 0) ? v1 : ((kx == 1) ? v2 : v3);
                float u2 = (kx == 0) ? v2 : ((kx == 1) ? v3 : v4);
                float u3 = (kx == 0) ? v3 : ((kx == 1) ? v4 : v5);

                acc[0][0] = fmaf(u0, wa.x, acc[0][0]);
                acc[0][1] = fmaf(u1, wa.x, acc[0][1]);
                acc[0][2] = fmaf(u2, wa.x, acc[0][2]);
                acc[0][3] = fmaf(u3, wa.x, acc[0][3]);
                acc[1][0] = fmaf(u0, wa.y, acc[1][0]);
                acc[1][1] = fmaf(u1, wa.y, acc[1][1]);
                acc[1][2] = fmaf(u2, wa.y, acc[1][2]);
                acc[1][3] = fmaf(u3, wa.y, acc[1][3]);
                acc[2][0] = fmaf(u0, wa.z, acc[2][0]);
                acc[2][1] = fmaf(u1, wa.z, acc[2][1]);
                acc[2][2] = fmaf(u2, wa.z, acc[2][2]);
                acc[2][3] = fmaf(u3, wa.z, acc[2][3]);
                acc[3][0] = fmaf(u0, wa.w, acc[3][0]);
                acc[3][1] = fmaf(u1, wa.w, acc[3][1]);
                acc[3][2] = fmaf(u2, wa.w, acc[3][2]);
                acc[3][3] = fmaf(u3, wa.w, acc[3][3]);
                acc[4][0] = fmaf(u0, wc.x, acc[4][0]);
                acc[4][1] = fmaf(u1, wc.x, acc[4][1]);
                acc[4][2] = fmaf(u2, wc.x, acc[4][2]);
                acc[4][3] = fmaf(u3, wc.x, acc[4][3]);
                acc[5][0] = fmaf(u0, wc.y, acc[5][0]);
                acc[5][1] = fmaf(u1, wc.y, acc[5][1]);
                acc[5][2] = fmaf(u2, wc.y, acc[5][2]);
                acc[5][3] = fmaf(u3, wc.y, acc[5][3]);
                acc[6][0] = fmaf(u0, wc.z, acc[6][0]);
                acc[6][1] = fmaf(u1, wc.z, acc[6][1]);
                acc[6][2] = fmaf(u2, wc.z, acc[6][2]);
                acc[6][3] = fmaf(u3, wc.z, acc[6][3]);
                acc[7][0] = fmaf(u0, wc.w, acc[7][0]);
                acc[7][1] = fmaf(u1, wc.w, acc[7][1]);
                acc[7][2] = fmaf(u2, wc.w, acc[7][2]);
                acc[7][3] = fmaf(u3, wc.w, acc[7][3]);
            }
        }
    }

    // ---- write out (relu), vectorized STG.128 ----
    float* outb = out + (size_t)n * 8 * PLANE + ((gy0 + ty) << 9) + gx0 + 4 * tx;
    #pragma unroll
    for (int oc = 0; oc < 8; ++oc) {
        float4 o;
        o.x = fmaxf(acc[oc][0], 0.0f);
        o.y = fmaxf(acc[oc][1], 0.0f);
        o.z = fmaxf(acc[oc][2], 0.0f);
        o.w = fmaxf(acc[oc][3], 0.0f);
        *(float4*)(outb + oc * PLANE) = o;
    }
}

// ---------------------------------------------------------------------------
// Generic scalar kernel (conv1: 1->8 relu, conv20: 8->1 no relu)
// ---------------------------------------------------------------------------
template <int IC, int OC, bool RELU>
__global__ void __launch_bounds__(256, 4)
conv3x3_kernel(const float* __restrict__ in,
               const float* __restrict__ wg,
               float* __restrict__ out)
{
    constexpr int TX = 32, TY = 32, RY = 4;
    constexpr int SW = TX + 2;
    constexpr int STILE = SW * (TY + 2);

    __shared__ float s_in[IC * STILE];
    __shared__ float s_w[IC * 9 * OC];

    const int tx  = threadIdx.x;
    const int ty  = threadIdx.y;
    const int tid = ty * 32 + tx;
    const int n   = blockIdx.z;
    const int gx0 = blockIdx.x * TX;
    const int gy0 = blockIdx.y * TY;

    const float* inb = in + (size_t)n * IC * PLANE;

    {
        const int gxA = gx0 + tx - 1;
        const bool xokA = (gxA >= 0) && (gxA < W);
        const int gxB = gx0 + 32 + tx - 1;
        const bool xokB = (tx < 2) && (gxB < W);

        #pragma unroll 1
        for (int ic = 0; ic < IC; ++ic) {
            const float* src = inb + ic * PLANE;
            float* dstS = &s_in[ic * STILE];
            #pragma unroll
            for (int j = 0; j < 5; ++j) {
                int sy = ty + j * 8;
                if (j == 4 && ty >= 2) continue;
                int gy = gy0 + sy - 1;
                bool yok = (gy >= 0) && (gy < H);
                int rb = (gy << 9);
                dstS[sy * SW + tx] = (yok && xokA) ? src[rb + gxA] : 0.0f;
                if (tx < 2)
                    dstS[sy * SW + 32 + tx] = (yok && xokB) ? src[rb + gxB] : 0.0f;
            }
        }
    }

    #pragma unroll 1
    for (int idx = tid; idx < IC * 9 * OC; idx += 256) {
        int oc = idx % OC;
        int t  = idx / OC;
        int ic = t / 9;
        int k  = t - ic * 9;
        s_w[idx] = wg[(oc * IC + ic) * 9 + k];
    }

    __syncthreads();

    float acc[RY][OC];
    #pragma unroll
    for (int ry = 0; ry < RY; ++ry)
        #pragma unroll
        for (int oc = 0; oc < OC; ++oc)
            acc[ry][oc] = 0.0f;

    const int y0 = ty * RY;
    const float* si0 = &s_in[y0 * SW + tx];

    #pragma unroll 1
    for (int ic = 0; ic < IC; ++ic) {
        const float* si = si0 + ic * STILE;
        const float* sw = &s_w[ic * 9 * OC];
        #pragma unroll
        for (int ky = 0; ky < 3; ++ky) {
            #pragma unroll
            for (int kx = 0; kx < 3; ++kx) {
                float wv[OC];
                #pragma unroll
                for (int oc = 0; oc < OC; ++oc)
                    wv[oc] = sw[(ky * 3 + kx) * OC + oc];
                #pragma unroll
                for (int ry = 0; ry < RY; ++ry) {
                    float v = si[(ry + ky) * SW + kx];
                    #pragma unroll
                    for (int oc = 0; oc < OC; ++oc)
                        acc[ry][oc] = fmaf(v, wv[oc], acc[ry][oc]);
                }
            }
        }
    }

    float* outb = out + (size_t)n * OC * PLANE;
    #pragma unroll
    for (int ry = 0; ry < RY; ++ry) {
        int off = ((gy0 + y0 + ry) << 9) + gx0 + tx;
        #pragma unroll
        for (int oc = 0; oc < OC; ++oc) {
            float v = acc[ry][oc];
            if (RELU) v = fmaxf(v, 0.0f);
            outb[oc * PLANE + off] = v;
        }
    }
}

extern "C" void kernel_launch(void* const* d_in, const int* in_sizes, int n_in,
                              void* d_out, int out_size)
{
    const float* x    = (const float*)d_in[0];  // [8,1,512,512]
    const float* w1   = (const float*)d_in[1];  // [8,1,3,3]
    const float* wmid = (const float*)d_in[2];  // [18,8,8,3,3]
    const float* w20  = (const float*)d_in[3];  // [1,8,3,3]
    float* out = (float*)d_out;                 // [8,1,512,512]

    float* bufA = nullptr;
    float* bufB = nullptr;
    float* wpack = nullptr;
    cudaGetSymbolAddress((void**)&bufA, g_bufA);
    cudaGetSymbolAddress((void**)&bufB, g_bufB);
    cudaGetSymbolAddress((void**)&wpack, g_wpack);

    // repack mid weights and stage them into the constant bank (capturable)
    repack_weights_kernel<<<(18 * 8 * 9 * 8 + 255) / 256, 256>>>(wmid);
    cudaMemcpyToSymbolAsync(c_w, wpack, 18 * 8 * 9 * 8 * sizeof(float), 0,
                            cudaMemcpyDeviceToDevice, 0);

    dim3 blockStd(32, 8);
    dim3 gridStd(W / 32, H / 32, NB);

    // conv1: 1 -> 8, relu
    conv3x3_kernel<1, 8, true><<<gridStd, blockStd>>>(x, w1, bufA);

    // conv2..19: 18x 8 -> 8, relu (pixel-vectorized, constant-bank weights)
    dim3 gridMid(W / 128, H / 8, NB);
    float* src = bufA;
    float* dst = bufB;
    for (int l = 0; l < 18; ++l) {
        conv3x3_88_kernel<<<gridMid, 256>>>(src, dst, l * 576);
        float* t = src; src = dst; dst = t;
    }

    // conv20: 8 -> 1, no relu
    conv3x3_kernel<8, 1, false><<<gridStd, blockStd>>>(src, w20, out);
}

// round 11
// speedup vs baseline: 2.3456x; 1.1562x over previous
#include <cuda_runtime.h>
#include <cuda_bf16.h>

// SmallVDSR: 20-layer 3x3 conv stack on [8,1,512,512] fp32.
//   conv1: 1->8 + relu
//   conv2..19: 18x (8->8 + relu)   [hot kernel]
//   conv20: 8->1, no relu
//
// R10 hot kernel: pixel-vectorized direct conv (R9) + f32x2 packed FMA over
// oc-pairs. Weights read from __constant__ as ulonglong2 -> oc-pair operands
// for free (layout [tap][oc0..7] is pair-aligned). Inputs dup-packed once
// per row (6 movs) and reused across kx. 144 FFMA2/ic instead of 288 FFMA.

#define H 512
#define W 512
#define NB 8
#define PLANE (H * W)

typedef unsigned long long u64;

__device__ float g_bufA[NB * 8 * PLANE];
__device__ float g_bufB[NB * 8 * PLANE];

// Mid-layer weights, repacked [l][ic][tap][oc] (oc contiguous): 18*8*9*8 floats.
__constant__ __align__(16) float c_w[18 * 8 * 9 * 8];
__device__   float g_wpack[18 * 8 * 9 * 8];

__device__ __forceinline__ u64 pack_dup(float v) {
    u64 r;
    asm("mov.b64 %0, {%1, %1};" : "=l"(r) : "f"(v));
    return r;
}
__device__ __forceinline__ void fma2(u64& acc, u64 a, u64 b) {
    asm("fma.rn.f32x2 %0, %1, %2, %0;" : "+l"(acc) : "l"(a), "l"(b));
}
__device__ __forceinline__ void unpack2(float& lo, float& hi, u64 v) {
    asm("mov.b64 {%0, %1}, %2;" : "=f"(lo), "=f"(hi) : "l"(v));
}

__global__ void repack_weights_kernel(const float* __restrict__ wmid)
{
    int idx = blockIdx.x * blockDim.x + threadIdx.x;   // [l][ic][t][oc]
    if (idx >= 18 * 8 * 9 * 8) return;
    int oc = idx & 7;
    int t  = (idx >> 3) % 9;
    int ic = ((idx >> 3) / 9) & 7;
    int l  = idx / 576;
    // source layout: [l][oc][ic][ky][kx]
    g_wpack[idx] = wmid[l * 576 + (oc * 8 + ic) * 9 + t];
}

// ---------------------------------------------------------------------------
// Mid layers: 8 -> 8, relu. Pixel-vectorized + f32x2 oc-pairs.
// Block 256. Tile 128x8 outputs. Thread: 4 px x 8 oc = 16 u64 accumulators.
// ---------------------------------------------------------------------------
__global__ void __launch_bounds__(256, 4)
conv3x3_88_kernel(const float* __restrict__ in,
                  float* __restrict__ out,
                  int lbase)                 // = layer * 576
{
    constexpr int TW = 128;               // tile width (outputs)
    constexpr int TH = 8;                 // tile height (outputs)
    constexpr int PITCH = 132;            // halo row pitch (130 used, 16B-aligned)
    constexpr int STILE = PITCH * (TH + 2);   // 1320 floats per ic

    __shared__ __align__(16) float s_in[8 * STILE];

    const int tid  = threadIdx.x;
    const int tx   = tid & 31;            // 0..31 -> cols 4tx..4tx+3
    const int ty   = tid >> 5;            // 0..7  -> output row
    const int n    = blockIdx.z;
    const int gx0  = blockIdx.x * TW;
    const int gy0  = blockIdx.y * TH;

    const float* inb = in + (size_t)n * 8 * PLANE;

    // ---- stage input tile 130x10 per ic (zero halo), warp-per-row ----
    {
        const int wid  = tid >> 5;
        const int lane = tid & 31;
        #pragma unroll 1
        for (int ic = 0; ic < 8; ++ic) {
            const float* src = inb + ic * PLANE;
            float* dst = &s_in[ic * STILE];
            #pragma unroll
            for (int rr0 = 0; rr0 < 2; ++rr0) {
                int rr = wid + rr0 * 8;
                if (rr0 == 1 && wid >= 2) continue;    // rows 8,9 by warps 0,1
                int gy = gy0 + rr - 1;
                bool yok = (gy >= 0) && (gy < H);
                int rb = gy << 9;
                #pragma unroll
                for (int cc = 0; cc < 5; ++cc) {
                    int c = lane + cc * 32;
                    if (cc == 4 && lane >= 2) break;   // cols 0..129
                    int gx = gx0 + c - 1;
                    bool ok = yok && (gx >= 0) && (gx < W);
                    dst[rr * PITCH + c] = ok ? src[rb + gx] : 0.0f;
                }
            }
        }
    }

    __syncthreads();

    u64 acc2[4][4];   // [oc-pair][px]
    #pragma unroll
    for (int p = 0; p < 4; ++p)
        #pragma unroll
        for (int j = 0; j < 4; ++j)
            acc2[p][j] = 0ull;

    // thread's input window base: halo rows ty..ty+2, halo cols 4tx..4tx+5
    const float* si0 = &s_in[ty * PITCH + 4 * tx];

    #pragma unroll 1
    for (int ic = 0; ic < 8; ++ic) {
        const float* si = si0 + ic * STILE;
        const int wb_ic = lbase + ic * 72;

        #pragma unroll
        for (int r = 0; r < 3; ++r) {                  // input row = ky
            float4 v03 = *(const float4*)(si + r * PITCH);
            float2 v45 = *(const float2*)(si + r * PITCH + 4);
            // dup-packed inputs, hoisted per row, reused across kx
            u64 dd[6];
            dd[0] = pack_dup(v03.x);
            dd[1] = pack_dup(v03.y);
            dd[2] = pack_dup(v03.z);
            dd[3] = pack_dup(v03.w);
            dd[4] = pack_dup(v45.x);
            dd[5] = pack_dup(v45.y);

            #pragma unroll
            for (int kx = 0; kx < 3; ++kx) {
                const int tb = wb_ic + (r * 3 + kx) * 8;
                // oc-pair weights straight from constant bank (LDC.128 x2)
                ulonglong2 wp0 = *(const ulonglong2*)&c_w[tb];     // (w0,w1),(w2,w3)
                ulonglong2 wp1 = *(const ulonglong2*)&c_w[tb + 4]; // (w4,w5),(w6,w7)

                #pragma unroll
                for (int j = 0; j < 4; ++j) {
                    u64 u = dd[j + kx];
                    fma2(acc2[0][j], u, wp0.x);
                    fma2(acc2[1][j], u, wp0.y);
                    fma2(acc2[2][j], u, wp1.x);
                    fma2(acc2[3][j], u, wp1.y);
                }
            }
        }
    }

    // ---- write out (relu), vectorized STG.128 ----
    float* outb = out + (size_t)n * 8 * PLANE + ((gy0 + ty) << 9) + gx0 + 4 * tx;
    #pragma unroll
    for (int p = 0; p < 4; ++p) {
        float l0, h0, l1, h1, l2, h2, l3, h3;
        unpack2(l0, h0, acc2[p][0]);
        unpack2(l1, h1, acc2[p][1]);
        unpack2(l2, h2, acc2[p][2]);
        unpack2(l3, h3, acc2[p][3]);
        float4 oL, oH;
        oL.x = fmaxf(l0, 0.0f); oL.y = fmaxf(l1, 0.0f);
        oL.z = fmaxf(l2, 0.0f); oL.w = fmaxf(l3, 0.0f);
        oH.x = fmaxf(h0, 0.0f); oH.y = fmaxf(h1, 0.0f);
        oH.z = fmaxf(h2, 0.0f); oH.w = fmaxf(h3, 0.0f);
        *(float4*)(outb + (2 * p + 0) * PLANE) = oL;
        *(float4*)(outb + (2 * p + 1) * PLANE) = oH;
    }
}

// ---------------------------------------------------------------------------
// Generic scalar kernel (conv1: 1->8 relu, conv20: 8->1 no relu)
// ---------------------------------------------------------------------------
template <int IC, int OC, bool RELU>
__global__ void __launch_bounds__(256, 4)
conv3x3_kernel(const float* __restrict__ in,
               const float* __restrict__ wg,
               float* __restrict__ out)
{
    constexpr int TX = 32, TY = 32, RY = 4;
    constexpr int SW = TX + 2;
    constexpr int STILE = SW * (TY + 2);

    __shared__ float s_in[IC * STILE];
    __shared__ float s_w[IC * 9 * OC];

    const int tx  = threadIdx.x;
    const int ty  = threadIdx.y;
    const int tid = ty * 32 + tx;
    const int n   = blockIdx.z;
    const int gx0 = blockIdx.x * TX;
    const int gy0 = blockIdx.y * TY;

    const float* inb = in + (size_t)n * IC * PLANE;

    {
        const int gxA = gx0 + tx - 1;
        const bool xokA = (gxA >= 0) && (gxA < W);
        const int gxB = gx0 + 32 + tx - 1;
        const bool xokB = (tx < 2) && (gxB < W);

        #pragma unroll 1
        for (int ic = 0; ic < IC; ++ic) {
            const float* src = inb + ic * PLANE;
            float* dstS = &s_in[ic * STILE];
            #pragma unroll
            for (int j = 0; j < 5; ++j) {
                int sy = ty + j * 8;
                if (j == 4 && ty >= 2) continue;
                int gy = gy0 + sy - 1;
                bool yok = (gy >= 0) && (gy < H);
                int rb = (gy << 9);
                dstS[sy * SW + tx] = (yok && xokA) ? src[rb + gxA] : 0.0f;
                if (tx < 2)
                    dstS[sy * SW + 32 + tx] = (yok && xokB) ? src[rb + gxB] : 0.0f;
            }
        }
    }

    #pragma unroll 1
    for (int idx = tid; idx < IC * 9 * OC; idx += 256) {
        int oc = idx % OC;
        int t  = idx / OC;
        int ic = t / 9;
        int k  = t - ic * 9;
        s_w[idx] = wg[(oc * IC + ic) * 9 + k];
    }

    __syncthreads();

    float acc[RY][OC];
    #pragma unroll
    for (int ry = 0; ry < RY; ++ry)
        #pragma unroll
        for (int oc = 0; oc < OC; ++oc)
            acc[ry][oc] = 0.0f;

    const int y0 = ty * RY;
    const float* si0 = &s_in[y0 * SW + tx];

    #pragma unroll 1
    for (int ic = 0; ic < IC; ++ic) {
        const float* si = si0 + ic * STILE;
        const float* sw = &s_w[ic * 9 * OC];
        #pragma unroll
        for (int ky = 0; ky < 3; ++ky) {
            #pragma unroll
            for (int kx = 0; kx < 3; ++kx) {
                float wv[OC];
                #pragma unroll
                for (int oc = 0; oc < OC; ++oc)
                    wv[oc] = sw[(ky * 3 + kx) * OC + oc];
                #pragma unroll
                for (int ry = 0; ry < RY; ++ry) {
                    float v = si[(ry + ky) * SW + kx];
                    #pragma unroll
                    for (int oc = 0; oc < OC; ++oc)
                        acc[ry][oc] = fmaf(v, wv[oc], acc[ry][oc]);
                }
            }
        }
    }

    float* outb = out + (size_t)n * OC * PLANE;
    #pragma unroll
    for (int ry = 0; ry < RY; ++ry) {
        int off = ((gy0 + y0 + ry) << 9) + gx0 + tx;
        #pragma unroll
        for (int oc = 0; oc < OC; ++oc) {
            float v = acc[ry][oc];
            if (RELU) v = fmaxf(v, 0.0f);
            outb[oc * PLANE + off] = v;
        }
    }
}

extern "C" void kernel_launch(void* const* d_in, const int* in_sizes, int n_in,
                              void* d_out, int out_size)
{
    const float* x    = (const float*)d_in[0];  // [8,1,512,512]
    const float* w1   = (const float*)d_in[1];  // [8,1,3,3]
    const float* wmid = (const float*)d_in[2];  // [18,8,8,3,3]
    const float* w20  = (const float*)d_in[3];  // [1,8,3,3]
    float* out = (float*)d_out;                 // [8,1,512,512]

    float* bufA = nullptr;
    float* bufB = nullptr;
    float* wpack = nullptr;
    cudaGetSymbolAddress((void**)&bufA, g_bufA);
    cudaGetSymbolAddress((void**)&bufB, g_bufB);
    cudaGetSymbolAddress((void**)&wpack, g_wpack);

    // repack mid weights and stage them into the constant bank (capturable)
    repack_weights_kernel<<<(18 * 8 * 9 * 8 + 255) / 256, 256>>>(wmid);
    cudaMemcpyToSymbolAsync(c_w, wpack, 18 * 8 * 9 * 8 * sizeof(float), 0,
                            cudaMemcpyDeviceToDevice, 0);

    dim3 blockStd(32, 8);
    dim3 gridStd(W / 32, H / 32, NB);

    // conv1: 1 -> 8, relu
    conv3x3_kernel<1, 8, true><<<gridStd, blockStd>>>(x, w1, bufA);

    // conv2..19: 18x 8 -> 8, relu (pixel-vectorized + f32x2 oc-pairs)
    dim3 gridMid(W / 128, H / 8, NB);
    float* src = bufA;
    float* dst = bufB;
    for (int l = 0; l < 18; ++l) {
        conv3x3_88_kernel<<<gridMid, 256>>>(src, dst, l * 576);
        float* t = src; src = dst; dst = t;
    }

    // conv20: 8 -> 1, no relu
    conv3x3_kernel<8, 1, false><<<gridStd, blockStd>>>(src, w20, out);
}

// round 12
// speedup vs baseline: 2.3871x; 1.0177x over previous
#include <cuda_runtime.h>
#include <cuda_bf16.h>

// SmallVDSR: 20-layer 3x3 conv stack on [8,1,512,512] fp32.
//   conv1: 1->8 + relu        (vectorized, IC=1)
//   conv2..19: 18x (8->8+relu) (hot kernel: pixel-vectorized + f32x2 + const weights)
//   conv20: 8->1, no relu     (vectorized, OC=1)
//
// R11: ic-loop unroll 2 (software pipelining across ic) + vectorized
// boundary layers with constant-bank weights.

#define H 512
#define W 512
#define NB 8
#define PLANE (H * W)

typedef unsigned long long u64;

__device__ float g_bufA[NB * 8 * PLANE];
__device__ float g_bufB[NB * 8 * PLANE];

// Constant weights:
//   [0 .. 10368)        mid layers, [l][ic][tap][oc]
//   [10368 .. 10440)    w1 repacked [ic=0][tap][oc]   (72)
//   [10440 .. 10512)    w20 repacked [ic][tap] (oc=1) (72)
#define CW_MID  0
#define CW_W1   (18 * 8 * 9 * 8)
#define CW_W20  (CW_W1 + 72)
__constant__ __align__(16) float c_w[CW_W20 + 72];
__device__   float g_wpack[CW_W20 + 72];

__device__ __forceinline__ u64 pack_dup(float v) {
    u64 r;
    asm("mov.b64 %0, {%1, %1};" : "=l"(r) : "f"(v));
    return r;
}
__device__ __forceinline__ void fma2(u64& acc, u64 a, u64 b) {
    asm("fma.rn.f32x2 %0, %1, %2, %0;" : "+l"(acc) : "l"(a), "l"(b));
}
__device__ __forceinline__ void unpack2(float& lo, float& hi, u64 v) {
    asm("mov.b64 {%0, %1}, %2;" : "=f"(lo), "=f"(hi) : "l"(v));
}

__global__ void repack_weights_kernel(const float* __restrict__ wmid,
                                      const float* __restrict__ w1,
                                      const float* __restrict__ w20)
{
    int idx = blockIdx.x * blockDim.x + threadIdx.x;
    if (idx < 18 * 8 * 9 * 8) {
        int oc = idx & 7;
        int t  = (idx >> 3) % 9;
        int ic = ((idx >> 3) / 9) & 7;
        int l  = idx / 576;
        g_wpack[idx] = wmid[l * 576 + (oc * 8 + ic) * 9 + t];   // [l][oc][ic][k]
    } else if (idx < 18 * 8 * 9 * 8 + 72) {
        int j = idx - 18 * 8 * 9 * 8;      // [tap][oc]
        int oc = j & 7;
        int t  = j >> 3;
        g_wpack[idx] = w1[oc * 9 + t];                           // [oc][0][k]
    } else if (idx < CW_W20 + 72) {
        int j = idx - CW_W20;              // [ic][tap]
        int t  = j % 9;
        int ic = j / 9;
        g_wpack[idx] = w20[ic * 9 + t];                          // [0][ic][k]
    }
}

// ---------------------------------------------------------------------------
// Shared staging: 130x10 halo tile per ic into smem (pitch 132).
// ---------------------------------------------------------------------------
template <int IC>
__device__ __forceinline__ void stage_tile(const float* __restrict__ inb,
                                           float* __restrict__ s_in,
                                           int gx0, int gy0, int tid)
{
    constexpr int PITCH = 132;
    constexpr int STILE = PITCH * 10;
    const int wid  = tid >> 5;
    const int lane = tid & 31;
    #pragma unroll 1
    for (int ic = 0; ic < IC; ++ic) {
        const float* src = inb + ic * PLANE;
        float* dst = s_in + ic * STILE;
        #pragma unroll
        for (int rr0 = 0; rr0 < 2; ++rr0) {
            int rr = wid + rr0 * 8;
            if (rr0 == 1 && wid >= 2) continue;    // rows 8,9 by warps 0,1
            int gy = gy0 + rr - 1;
            bool yok = (gy >= 0) && (gy < H);
            int rb = gy << 9;
            #pragma unroll
            for (int cc = 0; cc < 5; ++cc) {
                int c = lane + cc * 32;
                if (cc == 4 && lane >= 2) break;   // cols 0..129
                int gx = gx0 + c - 1;
                bool ok = yok && (gx >= 0) && (gx < W);
                dst[rr * PITCH + c] = ok ? src[rb + gx] : 0.0f;
            }
        }
    }
}

// ---------------------------------------------------------------------------
// Vectorized conv, OC=8 (f32x2 oc-pairs). IC = 8 (mid) or 1 (conv1).
// Block 256. Tile 128x8. Thread: 4 px x 8 oc.
// ---------------------------------------------------------------------------
template <int IC, int UNROLL>
__global__ void __launch_bounds__(256, 4)
convv8_kernel(const float* __restrict__ in,
              float* __restrict__ out,
              int wofs)
{
    constexpr int PITCH = 132;
    constexpr int STILE = PITCH * 10;

    __shared__ __align__(16) float s_in[IC * STILE];

    const int tid  = threadIdx.x;
    const int tx   = tid & 31;
    const int ty   = tid >> 5;
    const int n    = blockIdx.z;
    const int gx0  = blockIdx.x * 128;
    const int gy0  = blockIdx.y * 8;

    stage_tile<IC>(in + (size_t)n * IC * PLANE, s_in, gx0, gy0, tid);
    __syncthreads();

    u64 acc2[4][4];   // [oc-pair][px]
    #pragma unroll
    for (int p = 0; p < 4; ++p)
        #pragma unroll
        for (int j = 0; j < 4; ++j)
            acc2[p][j] = 0ull;

    const float* si0 = &s_in[ty * PITCH + 4 * tx];

    #pragma unroll UNROLL
    for (int ic = 0; ic < IC; ++ic) {
        const float* si = si0 + ic * STILE;
        const int wb_ic = wofs + ic * 72;

        #pragma unroll
        for (int r = 0; r < 3; ++r) {
            float4 v03 = *(const float4*)(si + r * PITCH);
            float2 v45 = *(const float2*)(si + r * PITCH + 4);
            u64 dd[6];
            dd[0] = pack_dup(v03.x);
            dd[1] = pack_dup(v03.y);
            dd[2] = pack_dup(v03.z);
            dd[3] = pack_dup(v03.w);
            dd[4] = pack_dup(v45.x);
            dd[5] = pack_dup(v45.y);

            #pragma unroll
            for (int kx = 0; kx < 3; ++kx) {
                const int tb = wb_ic + (r * 3 + kx) * 8;
                ulonglong2 wp0 = *(const ulonglong2*)&c_w[tb];
                ulonglong2 wp1 = *(const ulonglong2*)&c_w[tb + 4];
                #pragma unroll
                for (int j = 0; j < 4; ++j) {
                    u64 u = dd[j + kx];
                    fma2(acc2[0][j], u, wp0.x);
                    fma2(acc2[1][j], u, wp0.y);
                    fma2(acc2[2][j], u, wp1.x);
                    fma2(acc2[3][j], u, wp1.y);
                }
            }
        }
    }

    float* outb = out + (size_t)n * 8 * PLANE + ((gy0 + ty) << 9) + gx0 + 4 * tx;
    #pragma unroll
    for (int p = 0; p < 4; ++p) {
        float l0, h0, l1, h1, l2, h2, l3, h3;
        unpack2(l0, h0, acc2[p][0]);
        unpack2(l1, h1, acc2[p][1]);
        unpack2(l2, h2, acc2[p][2]);
        unpack2(l3, h3, acc2[p][3]);
        float4 oL, oH;
        oL.x = fmaxf(l0, 0.0f); oL.y = fmaxf(l1, 0.0f);
        oL.z = fmaxf(l2, 0.0f); oL.w = fmaxf(l3, 0.0f);
        oH.x = fmaxf(h0, 0.0f); oH.y = fmaxf(h1, 0.0f);
        oH.z = fmaxf(h2, 0.0f); oH.w = fmaxf(h3, 0.0f);
        *(float4*)(outb + (2 * p + 0) * PLANE) = oL;
        *(float4*)(outb + (2 * p + 1) * PLANE) = oH;
    }
}

// ---------------------------------------------------------------------------
// Vectorized conv20: IC=8 -> OC=1, no relu. Scalar accs (4 px).
// ---------------------------------------------------------------------------
__global__ void __launch_bounds__(256, 4)
convv20_kernel(const float* __restrict__ in,
               float* __restrict__ out)
{
    constexpr int PITCH = 132;
    constexpr int STILE = PITCH * 10;

    __shared__ __align__(16) float s_in[8 * STILE];

    const int tid  = threadIdx.x;
    const int tx   = tid & 31;
    const int ty   = tid >> 5;
    const int n    = blockIdx.z;
    const int gx0  = blockIdx.x * 128;
    const int gy0  = blockIdx.y * 8;

    stage_tile<8>(in + (size_t)n * 8 * PLANE, s_in, gx0, gy0, tid);
    __syncthreads();

    float acc[4] = {0.0f, 0.0f, 0.0f, 0.0f};
    const float* si0 = &s_in[ty * PITCH + 4 * tx];

    #pragma unroll 2
    for (int ic = 0; ic < 8; ++ic) {
        const float* si = si0 + ic * STILE;
        const int wb_ic = CW_W20 + ic * 9;

        #pragma unroll
        for (int r = 0; r < 3; ++r) {
            float4 v03 = *(const float4*)(si + r * PITCH);
            float2 v45 = *(const float2*)(si + r * PITCH + 4);
            float v[6] = {v03.x, v03.y, v03.z, v03.w, v45.x, v45.y};
            #pragma unroll
            for (int kx = 0; kx < 3; ++kx) {
                float w = c_w[wb_ic + r * 3 + kx];
                #pragma unroll
                for (int j = 0; j < 4; ++j)
                    acc[j] = fmaf(v[j + kx], w, acc[j]);
            }
        }
    }

    float* outb = out + (size_t)n * PLANE + ((gy0 + ty) << 9) + gx0 + 4 * tx;
    float4 o;
    o.x = acc[0]; o.y = acc[1]; o.z = acc[2]; o.w = acc[3];
    *(float4*)outb = o;
}

extern "C" void kernel_launch(void* const* d_in, const int* in_sizes, int n_in,
                              void* d_out, int out_size)
{
    const float* x    = (const float*)d_in[0];  // [8,1,512,512]
    const float* w1   = (const float*)d_in[1];  // [8,1,3,3]
    const float* wmid = (const float*)d_in[2];  // [18,8,8,3,3]
    const float* w20  = (const float*)d_in[3];  // [1,8,3,3]
    float* out = (float*)d_out;                 // [8,1,512,512]

    float* bufA = nullptr;
    float* bufB = nullptr;
    float* wpack = nullptr;
    cudaGetSymbolAddress((void**)&bufA, g_bufA);
    cudaGetSymbolAddress((void**)&bufB, g_bufB);
    cudaGetSymbolAddress((void**)&wpack, g_wpack);

    // repack all weights -> g_wpack -> constant bank (graph-capturable)
    const int nW = CW_W20 + 72;
    repack_weights_kernel<<<(nW + 255) / 256, 256>>>(wmid, w1, w20);
    cudaMemcpyToSymbolAsync(c_w, wpack, nW * sizeof(float), 0,
                            cudaMemcpyDeviceToDevice, 0);

    dim3 grid(W / 128, H / 8, NB);

    // conv1: 1 -> 8, relu
    convv8_kernel<1, 1><<<grid, 256>>>(x, bufA, CW_W1);

    // conv2..19: 18x 8 -> 8, relu (ic-unroll-2 pipelined)
    float* src = bufA;
    float* dst = bufB;
    for (int l = 0; l < 18; ++l) {
        convv8_kernel<8, 2><<<grid, 256>>>(src, dst, l * 576);
        float* t = src; src = dst; dst = t;
    }

    // conv20: 8 -> 1, no relu
    convv20_kernel<<<grid, 256>>>(src, out);
}

// round 13
// speedup vs baseline: 2.6139x; 1.0950x over previous
#include <cuda_runtime.h>
#include <cuda_bf16.h>

// SmallVDSR: 20-layer 3x3 conv stack on [8,1,512,512] fp32.
//   conv1: 1->8 + relu        (vectorized, IC=1)
//   conv2..19: 18x (8->8+relu) (hot kernel)
//   conv20: 8->1, no relu     (vectorized, OC=1)
//
// R12 hot kernel: R11 (pixel-vectorized + f32x2 oc-pairs) plus:
//   - __launch_bounds__(256,5): 5 CTAs/SM (regs pinned to 51)
//   - weight port split: oc0..3 pairs via smem LDS.128 broadcast,
//     oc4..7 pairs via constant-bank LDC.128 (halves const-port pressure)

#define H 512
#define W 512
#define NB 8
#define PLANE (H * W)

typedef unsigned long long u64;

__device__ float g_bufA[NB * 8 * PLANE];
__device__ float g_bufB[NB * 8 * PLANE];

// Packed weights, layout [l][ic][tap][oc] (oc contiguous):
//   [0 .. 10368)        mid layers
//   [10368 .. 10440)    w1  [tap][oc]
//   [10440 .. 10512)    w20 [ic][tap]
#define CW_MID  0
#define CW_W1   (18 * 8 * 9 * 8)
#define CW_W20  (CW_W1 + 72)
__constant__ __align__(16) float c_w[CW_W20 + 72];
__device__   __align__(16) float g_wpack[CW_W20 + 72];

__device__ __forceinline__ u64 pack_dup(float v) {
    u64 r;
    asm("mov.b64 %0, {%1, %1};" : "=l"(r) : "f"(v));
    return r;
}
__device__ __forceinline__ void fma2(u64& acc, u64 a, u64 b) {
    asm("fma.rn.f32x2 %0, %1, %2, %0;" : "+l"(acc) : "l"(a), "l"(b));
}
__device__ __forceinline__ void unpack2(float& lo, float& hi, u64 v) {
    asm("mov.b64 {%0, %1}, %2;" : "=f"(lo), "=f"(hi) : "l"(v));
}

__global__ void repack_weights_kernel(const float* __restrict__ wmid,
                                      const float* __restrict__ w1,
                                      const float* __restrict__ w20)
{
    int idx = blockIdx.x * blockDim.x + threadIdx.x;
    if (idx < 18 * 8 * 9 * 8) {
        int oc = idx & 7;
        int t  = (idx >> 3) % 9;
        int ic = ((idx >> 3) / 9) & 7;
        int l  = idx / 576;
        g_wpack[idx] = wmid[l * 576 + (oc * 8 + ic) * 9 + t];   // [l][oc][ic][k]
    } else if (idx < CW_W20) {
        int j = idx - CW_W1;               // [tap][oc]
        int oc = j & 7;
        int t  = j >> 3;
        g_wpack[idx] = w1[oc * 9 + t];                           // [oc][0][k]
    } else if (idx < CW_W20 + 72) {
        int j = idx - CW_W20;              // [ic][tap]
        int t  = j % 9;
        int ic = j / 9;
        g_wpack[idx] = w20[ic * 9 + t];                          // [0][ic][k]
    }
}

// ---------------------------------------------------------------------------
// Shared staging: 130x10 halo tile per ic into smem (pitch 132).
// ---------------------------------------------------------------------------
template <int IC>
__device__ __forceinline__ void stage_tile(const float* __restrict__ inb,
                                           float* __restrict__ s_in,
                                           int gx0, int gy0, int tid)
{
    constexpr int PITCH = 132;
    constexpr int STILE = PITCH * 10;
    const int wid  = tid >> 5;
    const int lane = tid & 31;
    #pragma unroll 1
    for (int ic = 0; ic < IC; ++ic) {
        const float* src = inb + ic * PLANE;
        float* dst = s_in + ic * STILE;
        #pragma unroll
        for (int rr0 = 0; rr0 < 2; ++rr0) {
            int rr = wid + rr0 * 8;
            if (rr0 == 1 && wid >= 2) continue;    // rows 8,9 by warps 0,1
            int gy = gy0 + rr - 1;
            bool yok = (gy >= 0) && (gy < H);
            int rb = gy << 9;
            #pragma unroll
            for (int cc = 0; cc < 5; ++cc) {
                int c = lane + cc * 32;
                if (cc == 4 && lane >= 2) break;   // cols 0..129
                int gx = gx0 + c - 1;
                bool ok = yok && (gx >= 0) && (gx < W);
                dst[rr * PITCH + c] = ok ? src[rb + gx] : 0.0f;
            }
        }
    }
}

// ---------------------------------------------------------------------------
// Vectorized conv, OC=8 (f32x2 oc-pairs). IC = 8 (mid) or 1 (conv1).
// Block 256. Tile 128x8. Thread: 4 px x 8 oc.
// Weights: oc0..3 pairs from smem (LDS.128), oc4..7 pairs from const (LDC.128).
// ---------------------------------------------------------------------------
template <int IC, int UNROLL, int MINB>
__global__ void __launch_bounds__(256, MINB)
convv8_kernel(const float* __restrict__ in,
              float* __restrict__ out,
              int wofs)
{
    constexpr int PITCH = 132;
    constexpr int STILE = PITCH * 10;

    __shared__ __align__(16) float s_in[IC * STILE];
    __shared__ __align__(16) u64   s_w[IC * 18];   // [ic][tap][pair01, pair23]

    const int tid  = threadIdx.x;
    const int tx   = tid & 31;
    const int ty   = tid >> 5;
    const int n    = blockIdx.z;
    const int gx0  = blockIdx.x * 128;
    const int gy0  = blockIdx.y * 8;

    // stage low-half weight pairs (oc0..3) into smem
    if (tid < IC * 18) {
        int ic = tid / 18;
        int r  = tid % 18;                 // tap*2 + p  (p selects oc01 / oc23)
        const float2 wv = *(const float2*)(g_wpack + wofs + ic * 72 + (r >> 1) * 8 + (r & 1) * 2);
        ((float2*)s_w)[tid] = wv;
    }

    stage_tile<IC>(in + (size_t)n * IC * PLANE, s_in, gx0, gy0, tid);
    __syncthreads();

    u64 acc2[4][4];   // [oc-pair][px]
    #pragma unroll
    for (int p = 0; p < 4; ++p)
        #pragma unroll
        for (int j = 0; j < 4; ++j)
            acc2[p][j] = 0ull;

    const float* si0 = &s_in[ty * PITCH + 4 * tx];

    #pragma unroll UNROLL
    for (int ic = 0; ic < IC; ++ic) {
        const float* si  = si0 + ic * STILE;
        const u64*   swp = &s_w[ic * 18];
        const int wb_ic  = wofs + ic * 72;

        #pragma unroll
        for (int r = 0; r < 3; ++r) {
            float4 v03 = *(const float4*)(si + r * PITCH);
            float2 v45 = *(const float2*)(si + r * PITCH + 4);
            u64 dd[6];
            dd[0] = pack_dup(v03.x);
            dd[1] = pack_dup(v03.y);
            dd[2] = pack_dup(v03.z);
            dd[3] = pack_dup(v03.w);
            dd[4] = pack_dup(v45.x);
            dd[5] = pack_dup(v45.y);

            #pragma unroll
            for (int kx = 0; kx < 3; ++kx) {
                const int t = r * 3 + kx;
                // oc0..3 pairs: smem broadcast LDS.128
                ulonglong2 wpA = *(const ulonglong2*)&swp[t * 2];
                // oc4..7 pairs: constant bank LDC.128
                ulonglong2 wpB = *(const ulonglong2*)&c_w[wb_ic + t * 8 + 4];
                #pragma unroll
                for (int j = 0; j < 4; ++j) {
                    u64 u = dd[j + kx];
                    fma2(acc2[0][j], u, wpA.x);
                    fma2(acc2[1][j], u, wpA.y);
                    fma2(acc2[2][j], u, wpB.x);
                    fma2(acc2[3][j], u, wpB.y);
                }
            }
        }
    }

    float* outb = out + (size_t)n * 8 * PLANE + ((gy0 + ty) << 9) + gx0 + 4 * tx;
    #pragma unroll
    for (int p = 0; p < 4; ++p) {
        float l0, h0, l1, h1, l2, h2, l3, h3;
        unpack2(l0, h0, acc2[p][0]);
        unpack2(l1, h1, acc2[p][1]);
        unpack2(l2, h2, acc2[p][2]);
        unpack2(l3, h3, acc2[p][3]);
        float4 oL, oH;
        oL.x = fmaxf(l0, 0.0f); oL.y = fmaxf(l1, 0.0f);
        oL.z = fmaxf(l2, 0.0f); oL.w = fmaxf(l3, 0.0f);
        oH.x = fmaxf(h0, 0.0f); oH.y = fmaxf(h1, 0.0f);
        oH.z = fmaxf(h2, 0.0f); oH.w = fmaxf(h3, 0.0f);
        *(float4*)(outb + (2 * p + 0) * PLANE) = oL;
        *(float4*)(outb + (2 * p + 1) * PLANE) = oH;
    }
}

// ---------------------------------------------------------------------------
// Vectorized conv20: IC=8 -> OC=1, no relu. Scalar accs (4 px).
// ---------------------------------------------------------------------------
__global__ void __launch_bounds__(256, 4)
convv20_kernel(const float* __restrict__ in,
               float* __restrict__ out)
{
    constexpr int PITCH = 132;
    constexpr int STILE = PITCH * 10;

    __shared__ __align__(16) float s_in[8 * STILE];

    const int tid  = threadIdx.x;
    const int tx   = tid & 31;
    const int ty   = tid >> 5;
    const int n    = blockIdx.z;
    const int gx0  = blockIdx.x * 128;
    const int gy0  = blockIdx.y * 8;

    stage_tile<8>(in + (size_t)n * 8 * PLANE, s_in, gx0, gy0, tid);
    __syncthreads();

    float acc[4] = {0.0f, 0.0f, 0.0f, 0.0f};
    const float* si0 = &s_in[ty * PITCH + 4 * tx];

    #pragma unroll 2
    for (int ic = 0; ic < 8; ++ic) {
        const float* si = si0 + ic * STILE;
        const int wb_ic = CW_W20 + ic * 9;

        #pragma unroll
        for (int r = 0; r < 3; ++r) {
            float4 v03 = *(const float4*)(si + r * PITCH);
            float2 v45 = *(const float2*)(si + r * PITCH + 4);
            float v[6] = {v03.x, v03.y, v03.z, v03.w, v45.x, v45.y};
            #pragma unroll
            for (int kx = 0; kx < 3; ++kx) {
                float w = c_w[wb_ic + r * 3 + kx];
                #pragma unroll
                for (int j = 0; j < 4; ++j)
                    acc[j] = fmaf(v[j + kx], w, acc[j]);
            }
        }
    }

    float* outb = out + (size_t)n * PLANE + ((gy0 + ty) << 9) + gx0 + 4 * tx;
    float4 o;
    o.x = acc[0]; o.y = acc[1]; o.z = acc[2]; o.w = acc[3];
    *(float4*)outb = o;
}

extern "C" void kernel_launch(void* const* d_in, const int* in_sizes, int n_in,
                              void* d_out, int out_size)
{
    const float* x    = (const float*)d_in[0];  // [8,1,512,512]
    const float* w1   = (const float*)d_in[1];  // [8,1,3,3]
    const float* wmid = (const float*)d_in[2];  // [18,8,8,3,3]
    const float* w20  = (const float*)d_in[3];  // [1,8,3,3]
    float* out = (float*)d_out;                 // [8,1,512,512]

    float* bufA = nullptr;
    float* bufB = nullptr;
    float* wpack = nullptr;
    cudaGetSymbolAddress((void**)&bufA, g_bufA);
    cudaGetSymbolAddress((void**)&bufB, g_bufB);
    cudaGetSymbolAddress((void**)&wpack, g_wpack);

    // repack all weights -> g_wpack -> constant bank (graph-capturable)
    const int nW = CW_W20 + 72;
    repack_weights_kernel<<<(nW + 255) / 256, 256>>>(wmid, w1, w20);
    cudaMemcpyToSymbolAsync(c_w, wpack, nW * sizeof(float), 0,
                            cudaMemcpyDeviceToDevice, 0);

    dim3 grid(W / 128, H / 8, NB);

    // conv1: 1 -> 8, relu
    convv8_kernel<1, 1, 4><<<grid, 256>>>(x, bufA, CW_W1);

    // conv2..19: 18x 8 -> 8, relu (occ-5, port-split weights)
    float* src = bufA;
    float* dst = bufB;
    for (int l = 0; l < 18; ++l) {
        convv8_kernel<8, 2, 5><<<grid, 256>>>(src, dst, l * 576);
        float* t = src; src = dst; dst = t;
    }

    // conv20: 8 -> 1, no relu
    convv20_kernel<<<grid, 256>>>(src, out);
}